// round 2
// baseline (speedup 1.0000x reference)
#include <cuda_runtime.h>
#include <math_constants.h>

// Problem shape (fixed by reference): B=2, N=2048, C=1024, H=16, D=64
#define BV 2
#define NV 2048
#define CV 1024
#define HV 16
#define DV 64
#define ATTN_SCALE 0.125f   // 64^-0.5

// Scratch (allocation-free rule: __device__ globals)
__device__ float g_Q[BV * NV * CV];        // 16 MB
__device__ float g_KV[BV * NV * 2 * CV];   // 32 MB
__device__ float g_A[BV * NV * CV];        // 16 MB

// ---------------------------------------------------------------------------
// SGEMM: C[M,N] = A[M,K] @ B[K,N] (+ bias[N]). 128x128 tile, Ktile=16,
// 256 threads, 8x8 micro-tile per thread, float4 global ld/st.
// Requires M%128==0, N%128==0, K%16==0 (true for all three calls).
// ---------------------------------------------------------------------------
__global__ __launch_bounds__(256, 2)
void sgemm128(const float* __restrict__ A, const float* __restrict__ Bm,
              const float* __restrict__ bias, float* __restrict__ C,
              int M, int N, int K)
{
    __shared__ float As[16][128];
    __shared__ float Bs[16][128];

    const int tid  = threadIdx.x;
    const int bm   = blockIdx.y * 128;
    const int bn   = blockIdx.x * 128;
    const int arow = tid >> 2;
    const int ak   = (tid & 3) << 2;
    const int brow = tid >> 5;
    const int bcol = (tid & 31) << 2;
    const int tx   = tid & 15;
    const int ty   = tid >> 4;

    float acc[8][8];
#pragma unroll
    for (int i = 0; i < 8; i++)
#pragma unroll
        for (int j = 0; j < 8; j++) acc[i][j] = 0.f;

    for (int k0 = 0; k0 < K; k0 += 16) {
        float4 a0 = *(const float4*)&A[(size_t)(bm + arow)      * K + k0 + ak];
        float4 a1 = *(const float4*)&A[(size_t)(bm + arow + 64) * K + k0 + ak];
        float4 b0 = *(const float4*)&Bm[(size_t)(k0 + brow)     * N + bn + bcol];
        float4 b1 = *(const float4*)&Bm[(size_t)(k0 + brow + 8) * N + bn + bcol];

        As[ak + 0][arow] = a0.x; As[ak + 1][arow] = a0.y;
        As[ak + 2][arow] = a0.z; As[ak + 3][arow] = a0.w;
        As[ak + 0][arow + 64] = a1.x; As[ak + 1][arow + 64] = a1.y;
        As[ak + 2][arow + 64] = a1.z; As[ak + 3][arow + 64] = a1.w;
        *(float4*)&Bs[brow][bcol]     = b0;
        *(float4*)&Bs[brow + 8][bcol] = b1;
        __syncthreads();

#pragma unroll
        for (int k = 0; k < 16; k++) {
            float a[8], b[8];
            *(float4*)&a[0] = *(const float4*)&As[k][ty * 8];
            *(float4*)&a[4] = *(const float4*)&As[k][ty * 8 + 4];
            *(float4*)&b[0] = *(const float4*)&Bs[k][tx * 8];
            *(float4*)&b[4] = *(const float4*)&Bs[k][tx * 8 + 4];
#pragma unroll
            for (int i = 0; i < 8; i++)
#pragma unroll
                for (int j = 0; j < 8; j++)
                    acc[i][j] = fmaf(a[i], b[j], acc[i][j]);
        }
        __syncthreads();
    }

    float bb[8];
#pragma unroll
    for (int j = 0; j < 8; j++) bb[j] = bias ? bias[bn + tx * 8 + j] : 0.f;

#pragma unroll
    for (int i = 0; i < 8; i++) {
        size_t row = (size_t)(bm + ty * 8 + i);
#pragma unroll
        for (int j0 = 0; j0 < 8; j0 += 4) {
            float4 r;
            r.x = acc[i][j0 + 0] + bb[j0 + 0];
            r.y = acc[i][j0 + 1] + bb[j0 + 1];
            r.z = acc[i][j0 + 2] + bb[j0 + 2];
            r.w = acc[i][j0 + 3] + bb[j0 + 3];
            *(float4*)&C[row * N + bn + tx * 8 + j0] = r;
        }
    }
}

// ---------------------------------------------------------------------------
// Flash-attention fp32. One block per (q-tile of 64 rows, b*H+h).
// 256 threads as 16x16: thread (tx,ty) owns score rows 4ty..4ty+3,
// score cols 2tx..2tx+1 (chunk of 32 keys), output dims 4tx..4tx+3.
// Q is pre-scaled by ATTN_SCALE on load. Online softmax across 64 chunks.
// NOTE: smem rows are padded to 65 floats -> NO vector ld/st into these
// arrays (65*4 bytes is not 16B aligned); scalar only.
// ---------------------------------------------------------------------------
__global__ __launch_bounds__(256)
void attn64(const float* __restrict__ Q, const float* __restrict__ KV,
            float* __restrict__ O)
{
    __shared__ float Qs[64][65];
    __shared__ float Ks[32][65];
    __shared__ float Vs[32][65];
    __shared__ float Ps[64][33];

    const int tid = threadIdx.x;
    const int tx  = tid & 15;
    const int ty  = tid >> 4;
    const int qt  = blockIdx.x;          // query tile 0..31
    const int b   = blockIdx.y >> 4;     // batch
    const int h   = blockIdx.y & 15;     // head

    const float* qbase = Q  + ((size_t)(b * NV + qt * 64)) * CV + h * DV;
    const float* kbase = KV + (size_t)b * NV * 2 * CV + h * DV;
    const float* vbase = kbase + CV;

    // Load Q tile (64x64), pre-scaled (scalar smem stores)
    for (int i = tid; i < 64 * 16; i += 256) {
        int r = i >> 4, c = (i & 15) << 2;
        float4 v = *(const float4*)&qbase[(size_t)r * CV + c];
        Qs[r][c + 0] = v.x * ATTN_SCALE;
        Qs[r][c + 1] = v.y * ATTN_SCALE;
        Qs[r][c + 2] = v.z * ATTN_SCALE;
        Qs[r][c + 3] = v.w * ATTN_SCALE;
    }

    float m[4], l[4], o[4][4];
#pragma unroll
    for (int i = 0; i < 4; i++) {
        m[i] = -CUDART_INF_F; l[i] = 0.f;
#pragma unroll
        for (int k = 0; k < 4; k++) o[i][k] = 0.f;
    }

    for (int c0 = 0; c0 < NV; c0 += 32) {
        __syncthreads();   // covers Q load (iter 0) and prior PV reads of Ks/Vs
        for (int i = tid; i < 32 * 16; i += 256) {
            int r = i >> 4, c = (i & 15) << 2;
            float4 kvec = *(const float4*)&kbase[(size_t)(c0 + r) * (2 * CV) + c];
            float4 vvec = *(const float4*)&vbase[(size_t)(c0 + r) * (2 * CV) + c];
            Ks[r][c + 0] = kvec.x; Ks[r][c + 1] = kvec.y;
            Ks[r][c + 2] = kvec.z; Ks[r][c + 3] = kvec.w;
            Vs[r][c + 0] = vvec.x; Vs[r][c + 1] = vvec.y;
            Vs[r][c + 2] = vvec.z; Vs[r][c + 3] = vvec.w;
        }
        __syncthreads();

        // S = Qs @ Ks^T  (64x32), per-thread 4x2
        float s[4][2];
#pragma unroll
        for (int i = 0; i < 4; i++) { s[i][0] = 0.f; s[i][1] = 0.f; }
#pragma unroll 8
        for (int d = 0; d < 64; d++) {
            float qv[4], kv2[2];
#pragma unroll
            for (int i = 0; i < 4; i++) qv[i] = Qs[ty * 4 + i][d];
            kv2[0] = Ks[tx * 2 + 0][d];
            kv2[1] = Ks[tx * 2 + 1][d];
#pragma unroll
            for (int i = 0; i < 4; i++) {
                s[i][0] = fmaf(qv[i], kv2[0], s[i][0]);
                s[i][1] = fmaf(qv[i], kv2[1], s[i][1]);
            }
        }

        // Online softmax (row groups are 16 consecutive lanes -> width-16 shfl)
#pragma unroll
        for (int i = 0; i < 4; i++) {
            float cm = fmaxf(s[i][0], s[i][1]);
#pragma unroll
            for (int off = 8; off; off >>= 1)
                cm = fmaxf(cm, __shfl_xor_sync(0xffffffffu, cm, off, 16));
            float mn  = fmaxf(m[i], cm);
            float fac = __expf(m[i] - mn);
            float p0  = __expf(s[i][0] - mn);
            float p1  = __expf(s[i][1] - mn);
            float rs  = p0 + p1;
#pragma unroll
            for (int off = 8; off; off >>= 1)
                rs += __shfl_xor_sync(0xffffffffu, rs, off, 16);
            l[i] = l[i] * fac + rs;
            m[i] = mn;
#pragma unroll
            for (int k = 0; k < 4; k++) o[i][k] *= fac;
            Ps[ty * 4 + i][tx * 2 + 0] = p0;
            Ps[ty * 4 + i][tx * 2 + 1] = p1;
        }
        __syncthreads();

        // O += P @ V  (64x64 += 64x32 @ 32x64), per-thread 4x4
#pragma unroll 4
        for (int j = 0; j < 32; j++) {
            float pv[4], vv[4];
#pragma unroll
            for (int i = 0; i < 4; i++) pv[i] = Ps[ty * 4 + i][j];
#pragma unroll
            for (int k = 0; k < 4; k++) vv[k] = Vs[j][tx * 4 + k];
#pragma unroll
            for (int i = 0; i < 4; i++)
#pragma unroll
                for (int k = 0; k < 4; k++)
                    o[i][k] = fmaf(pv[i], vv[k], o[i][k]);
        }
    }

    // Write normalized output into [B,N,C] scratch (head-interleaved)
#pragma unroll
    for (int i = 0; i < 4; i++) {
        float inv = 1.f / l[i];
        size_t row = (size_t)(b * NV + qt * 64 + ty * 4 + i);
        float4 r;
        r.x = o[i][0] * inv; r.y = o[i][1] * inv;
        r.z = o[i][2] * inv; r.w = o[i][3] * inv;
        *(float4*)&O[row * CV + h * DV + tx * 4] = r;
    }
}

// ---------------------------------------------------------------------------
extern "C" void kernel_launch(void* const* d_in, const int* in_sizes, int n_in,
                              void* d_out, int out_size)
{
    const float* x_t    = (const float*)d_in[0];
    const float* x_s    = (const float*)d_in[1];
    const float* W_q    = (const float*)d_in[2];
    const float* W_kv   = (const float*)d_in[3];
    const float* W_fuse = (const float*)d_in[4];
    const float* b_fuse = (const float*)d_in[5];
    float* out = (float*)d_out;

    float *Qp, *KVp, *Ap;
    cudaGetSymbolAddress((void**)&Qp,  g_Q);
    cudaGetSymbolAddress((void**)&KVp, g_KV);
    cudaGetSymbolAddress((void**)&Ap,  g_A);

    const int M = BV * NV;  // 4096
    dim3 blk(256);

    // Q = x_t @ W_q            [4096,1024] = [4096,1024]@[1024,1024]
    sgemm128<<<dim3(CV / 128, M / 128), blk>>>(x_t, W_q, nullptr, Qp, M, CV, CV);
    // KV = x_s @ W_kv          [4096,2048] = [4096,1024]@[1024,2048]
    sgemm128<<<dim3(2 * CV / 128, M / 128), blk>>>(x_s, W_kv, nullptr, KVp, M, 2 * CV, CV);
    // A = softmax(Q K^T * scale) V   -> [B,N,C]
    attn64<<<dim3(NV / 64, BV * HV), blk>>>(Qp, KVp, Ap);
    // out = A @ W_fuse + b_fuse
    sgemm128<<<dim3(CV / 128, M / 128), blk>>>(Ap, W_fuse, b_fuse, out, M, CV, CV);
}

// round 4
// speedup vs baseline: 2.9322x; 2.9322x over previous
#include <cuda_runtime.h>
#include <math_constants.h>
#include <cstdint>

// Problem shape (fixed): B=2, N=2048, C=1024, H=16, D=64
#define BV 2
#define NV 2048
#define CV 1024
#define HV 16
#define DV 64
#define ATTN_SCALE 0.125f

// Scratch (__device__ globals; allocation-free rule)
__device__ float g_Q [BV * NV * CV];
__device__ float g_KV[BV * NV * 2 * CV];
__device__ float g_A [BV * NV * CV];
__device__ float g_WqT [CV * CV];
__device__ float g_WkvT[2 * CV * CV];
__device__ float g_WfT [CV * CV];

// ---------------------------------------------------------------------------
// helpers
// ---------------------------------------------------------------------------
__device__ __forceinline__ uint32_t f2tf(float x) {  // fp32 -> tf32 (RNA)
    uint32_t r;
    asm("cvt.rna.tf32.f32 %0, %1;" : "=r"(r) : "f"(x));
    return r;
}
__device__ __forceinline__ void mma_tf32(float* d, const uint32_t* a,
                                         const uint32_t* b) {
    asm volatile(
        "mma.sync.aligned.m16n8k8.row.col.f32.tf32.tf32.f32 "
        "{%0,%1,%2,%3}, {%4,%5,%6,%7}, {%8,%9}, {%0,%1,%2,%3};"
        : "+f"(d[0]), "+f"(d[1]), "+f"(d[2]), "+f"(d[3])
        : "r"(a[0]), "r"(a[1]), "r"(a[2]), "r"(a[3]), "r"(b[0]), "r"(b[1]));
}

// ---------------------------------------------------------------------------
// Weight transpose: Wt[n*K + k] = W[k*N + n]
// ---------------------------------------------------------------------------
__global__ void transp(const float* __restrict__ W, float* __restrict__ Wt,
                       int K, int N)
{
    __shared__ float t[32][33];
    int k0 = blockIdx.y * 32, n0 = blockIdx.x * 32;
    int x = threadIdx.x, y = threadIdx.y;
#pragma unroll
    for (int j = 0; j < 32; j += 8)
        t[y + j][x] = W[(size_t)(k0 + y + j) * N + n0 + x];
    __syncthreads();
#pragma unroll
    for (int j = 0; j < 32; j += 8)
        Wt[(size_t)(n0 + y + j) * K + k0 + x] = t[x][y + j];
}

// ---------------------------------------------------------------------------
// Tensor-core tf32 GEMM: C[M,N] = A[M,K] @ Bt[N,K]^T (+bias).
// 128x128 tile, 256 threads / 8 warps, warp tile 64x32, K chunk 32.
// Smem rows padded to 36 words -> conflict-free fragment LDS.
// Double-buffered smem with register prefetch of the next chunk.
// ---------------------------------------------------------------------------
#define GEMM_SMEM (4 * 128 * 36 * 4)   // 73728 B

__global__ __launch_bounds__(256, 1)
void tcgemm(const float* __restrict__ A, const float* __restrict__ Bt,
            const float* __restrict__ bias, float* __restrict__ C,
            int M, int N, int K)
{
    extern __shared__ __align__(16) uint32_t sm[];
    // layout (words): Abuf0 [0,4608) Abuf1 [4608,9216) Bbuf0 [9216,..) Bbuf1
    const int tid = threadIdx.x;
    const int wid = tid >> 5, lid = tid & 31;
    const int bm = blockIdx.y * 128, bn = blockIdx.x * 128;
    const int wm = (wid & 1) * 64;       // warp M offset in tile
    const int wn = (wid >> 1) * 32;      // warp N offset in tile

    float acc[4][4][4];
#pragma unroll
    for (int mt = 0; mt < 4; mt++)
#pragma unroll
        for (int nt = 0; nt < 4; nt++)
#pragma unroll
            for (int r = 0; r < 4; r++) acc[mt][nt][r] = 0.f;

    const int NC = K >> 5;
    float4 ra[4], rb[4];

    // prefetch chunk 0
#pragma unroll
    for (int it = 0; it < 4; it++) {
        int s = tid + it * 256;
        int r = s >> 3, c4 = (s & 7) << 2;
        ra[it] = *(const float4*)&A [(size_t)(bm + r) * K + c4];
        rb[it] = *(const float4*)&Bt[(size_t)(bn + r) * K + c4];
    }
    // store chunk 0
#pragma unroll
    for (int it = 0; it < 4; it++) {
        int s = tid + it * 256;
        int r = s >> 3, c4 = (s & 7) << 2;
        uint4 pa = make_uint4(f2tf(ra[it].x), f2tf(ra[it].y), f2tf(ra[it].z), f2tf(ra[it].w));
        uint4 pb = make_uint4(f2tf(rb[it].x), f2tf(rb[it].y), f2tf(rb[it].z), f2tf(rb[it].w));
        *(uint4*)&sm[r * 36 + c4]        = pa;
        *(uint4*)&sm[9216 + r * 36 + c4] = pb;
    }
    __syncthreads();

    for (int c = 0; c < NC; c++) {
        if (c + 1 < NC) {
            int kc = (c + 1) << 5;
#pragma unroll
            for (int it = 0; it < 4; it++) {
                int s = tid + it * 256;
                int r = s >> 3, c4 = (s & 7) << 2;
                ra[it] = *(const float4*)&A [(size_t)(bm + r) * K + kc + c4];
                rb[it] = *(const float4*)&Bt[(size_t)(bn + r) * K + kc + c4];
            }
        }
        const uint32_t* Ab = sm + (c & 1) * 4608;
        const uint32_t* Bb = sm + 9216 + (c & 1) * 4608;
#pragma unroll
        for (int ks = 0; ks < 4; ks++) {
            const int c0 = ks * 8 + (lid & 3);
            const int r0 = wm + (lid >> 2);
            uint32_t af[4][4], bf[4][2];
#pragma unroll
            for (int mt = 0; mt < 4; mt++) {
                const uint32_t* base = Ab + (r0 + mt * 16) * 36;
                af[mt][0] = base[c0];
                af[mt][1] = base[8 * 36 + c0];
                af[mt][2] = base[c0 + 4];
                af[mt][3] = base[8 * 36 + c0 + 4];
            }
            const int n0 = wn + (lid >> 2);
#pragma unroll
            for (int nt = 0; nt < 4; nt++) {
                const uint32_t* base = Bb + (n0 + nt * 8) * 36;
                bf[nt][0] = base[c0];
                bf[nt][1] = base[c0 + 4];
            }
#pragma unroll
            for (int mt = 0; mt < 4; mt++)
#pragma unroll
                for (int nt = 0; nt < 4; nt++)
                    mma_tf32(acc[mt][nt], af[mt], bf[nt]);
        }
        if (c + 1 < NC) {
            __syncthreads();
            uint32_t* Ab2 = sm + ((c + 1) & 1) * 4608;
            uint32_t* Bb2 = sm + 9216 + ((c + 1) & 1) * 4608;
#pragma unroll
            for (int it = 0; it < 4; it++) {
                int s = tid + it * 256;
                int r = s >> 3, c4 = (s & 7) << 2;
                uint4 pa = make_uint4(f2tf(ra[it].x), f2tf(ra[it].y), f2tf(ra[it].z), f2tf(ra[it].w));
                uint4 pb = make_uint4(f2tf(rb[it].x), f2tf(rb[it].y), f2tf(rb[it].z), f2tf(rb[it].w));
                *(uint4*)&Ab2[r * 36 + c4] = pa;
                *(uint4*)&Bb2[r * 36 + c4] = pb;
            }
            __syncthreads();
        }
    }

    // epilogue: D frag c0/c1 at (row, col..col+1), c2/c3 at (row+8, ...)
#pragma unroll
    for (int mt = 0; mt < 4; mt++) {
        int row = bm + wm + mt * 16 + (lid >> 2);
#pragma unroll
        for (int nt = 0; nt < 4; nt++) {
            int col = bn + wn + nt * 8 + 2 * (lid & 3);
            float b0 = bias ? bias[col] : 0.f;
            float b1 = bias ? bias[col + 1] : 0.f;
            float2 lo = make_float2(acc[mt][nt][0] + b0, acc[mt][nt][1] + b1);
            float2 hi = make_float2(acc[mt][nt][2] + b0, acc[mt][nt][3] + b1);
            *(float2*)&C[(size_t)row * N + col]       = lo;
            *(float2*)&C[(size_t)(row + 8) * N + col] = hi;
        }
    }
}

// ---------------------------------------------------------------------------
// Tensor-core flash attention (tf32 mma). Block = 128 threads / 4 warps.
// Block covers 64 q-rows of one (b,h); warp w owns q-rows [16w,16w+16).
// Keys processed in chunks of 32. S = Q@K^T via mma (warp tile 16x32),
// online softmax on D-fragments, P staged in smem, O += P@V via mma.
// ---------------------------------------------------------------------------
__global__ __launch_bounds__(128)
void tcattn(const float* __restrict__ Q, const float* __restrict__ KV,
            float* __restrict__ O)
{
    __shared__ uint32_t Qs[64][68];   // tf32 bits, pad 68 -> frag LDS conflict-free
    __shared__ uint32_t Ks[32][68];
    __shared__ uint32_t Vs[32][68];
    __shared__ uint32_t Ps[64][36];

    const int tid  = threadIdx.x;
    const int wid  = tid >> 5, lid = tid & 31;
    const int qt   = blockIdx.x;
    const int b    = blockIdx.y >> 4;
    const int h    = blockIdx.y & 15;

    const float* qbase = Q  + ((size_t)(b * NV + qt * 64)) * CV + h * DV;
    const float* kbase = KV + (size_t)b * NV * 2 * CV + h * DV;
    const float* vbase = kbase + CV;

    // load Q tile (scaled, tf32)
#pragma unroll
    for (int it = 0; it < 8; it++) {
        int s = tid + it * 128;
        int r = s >> 4, c4 = (s & 15) << 2;
        float4 v = *(const float4*)&qbase[(size_t)r * CV + c4];
        uint4 p = make_uint4(f2tf(v.x * ATTN_SCALE), f2tf(v.y * ATTN_SCALE),
                             f2tf(v.z * ATTN_SCALE), f2tf(v.w * ATTN_SCALE));
        *(uint4*)&Qs[r][c4] = p;
    }

    float o[8][4];
#pragma unroll
    for (int nt = 0; nt < 8; nt++)
#pragma unroll
        for (int r = 0; r < 4; r++) o[nt][r] = 0.f;
    float m0 = -CUDART_INF_F, m1 = -CUDART_INF_F, l0 = 0.f, l1 = 0.f;

    const int qrow = (lid >> 2);          // 0..7 within warp's 16 rows
    const int qc   = (lid & 3);

    for (int c0k = 0; c0k < NV; c0k += 32) {
        __syncthreads();   // protect Ks/Vs (prev iter readers) + Qs on iter 0
#pragma unroll
        for (int it = 0; it < 4; it++) {
            int s = tid + it * 128;
            int r = s >> 4, c4 = (s & 15) << 2;
            float4 kv = *(const float4*)&kbase[(size_t)(c0k + r) * (2 * CV) + c4];
            float4 vv = *(const float4*)&vbase[(size_t)(c0k + r) * (2 * CV) + c4];
            *(uint4*)&Ks[r][c4] = make_uint4(f2tf(kv.x), f2tf(kv.y), f2tf(kv.z), f2tf(kv.w));
            *(uint4*)&Vs[r][c4] = make_uint4(f2tf(vv.x), f2tf(vv.y), f2tf(vv.z), f2tf(vv.w));
        }
        __syncthreads();

        // ---- S = Q @ K^T : warp tile 16x32, 4 ntiles, 8 ksteps over D=64
        float s[4][4];
#pragma unroll
        for (int nt = 0; nt < 4; nt++)
#pragma unroll
            for (int r = 0; r < 4; r++) s[nt][r] = 0.f;
#pragma unroll
        for (int ks = 0; ks < 8; ks++) {
            const int cc = ks * 8 + qc;
            uint32_t af[4], bf[4][2];
            const uint32_t* qb = &Qs[wid * 16 + qrow][0];
            af[0] = qb[cc];
            af[1] = qb[8 * 68 + cc];
            af[2] = qb[cc + 4];
            af[3] = qb[8 * 68 + cc + 4];
#pragma unroll
            for (int nt = 0; nt < 4; nt++) {
                const uint32_t* kb = &Ks[nt * 8 + qrow][0];
                bf[nt][0] = kb[cc];
                bf[nt][1] = kb[cc + 4];
            }
#pragma unroll
            for (int nt = 0; nt < 4; nt++)
                mma_tf32(s[nt], af, bf[nt]);
        }

        // ---- online softmax on fragments
        // thread's rows: r0 = qrow, r1 = qrow+8 ; cols: nt*8 + 2*qc + {0,1}
        float mx0 = -CUDART_INF_F, mx1 = -CUDART_INF_F;
#pragma unroll
        for (int nt = 0; nt < 4; nt++) {
            mx0 = fmaxf(mx0, fmaxf(s[nt][0], s[nt][1]));
            mx1 = fmaxf(mx1, fmaxf(s[nt][2], s[nt][3]));
        }
        mx0 = fmaxf(mx0, __shfl_xor_sync(0xffffffffu, mx0, 1));
        mx0 = fmaxf(mx0, __shfl_xor_sync(0xffffffffu, mx0, 2));
        mx1 = fmaxf(mx1, __shfl_xor_sync(0xffffffffu, mx1, 1));
        mx1 = fmaxf(mx1, __shfl_xor_sync(0xffffffffu, mx1, 2));
        float mn0 = fmaxf(m0, mx0), mn1 = fmaxf(m1, mx1);
        float f0 = __expf(m0 - mn0), f1 = __expf(m1 - mn1);

        float rs0 = 0.f, rs1 = 0.f;
        const int pr0 = wid * 16 + qrow;
#pragma unroll
        for (int nt = 0; nt < 4; nt++) {
            float p0 = __expf(s[nt][0] - mn0);
            float p1 = __expf(s[nt][1] - mn0);
            float p2 = __expf(s[nt][2] - mn1);
            float p3 = __expf(s[nt][3] - mn1);
            rs0 += p0 + p1;
            rs1 += p2 + p3;
            int pc = nt * 8 + 2 * qc;
            *(uint2*)&Ps[pr0][pc]     = make_uint2(f2tf(p0), f2tf(p1));
            *(uint2*)&Ps[pr0 + 8][pc] = make_uint2(f2tf(p2), f2tf(p3));
        }
        rs0 += __shfl_xor_sync(0xffffffffu, rs0, 1);
        rs0 += __shfl_xor_sync(0xffffffffu, rs0, 2);
        rs1 += __shfl_xor_sync(0xffffffffu, rs1, 1);
        rs1 += __shfl_xor_sync(0xffffffffu, rs1, 2);
        l0 = l0 * f0 + rs0;  m0 = mn0;
        l1 = l1 * f1 + rs1;  m1 = mn1;
#pragma unroll
        for (int nt = 0; nt < 8; nt++) {
            o[nt][0] *= f0; o[nt][1] *= f0;
            o[nt][2] *= f1; o[nt][3] *= f1;
        }
        __syncwarp();

        // ---- O += P @ V : 4 ksteps over 32 keys, 8 ntiles over D=64
#pragma unroll
        for (int ks = 0; ks < 4; ks++) {
            const int kk = ks * 8 + qc;
            uint32_t af[4];
            const uint32_t* pb = &Ps[wid * 16 + qrow][0];
            af[0] = pb[kk];
            af[1] = pb[8 * 36 + kk];
            af[2] = pb[kk + 4];
            af[3] = pb[8 * 36 + kk + 4];
#pragma unroll
            for (int nt = 0; nt < 8; nt++) {
                uint32_t bf[2];
                bf[0] = Vs[ks * 8 + qc][nt * 8 + qrow];
                bf[1] = Vs[ks * 8 + qc + 4][nt * 8 + qrow];
                mma_tf32(o[nt], af, bf);
            }
        }
        __syncwarp();   // Ps reused next iteration
    }

    // ---- write O (normalized) to scratch [B*N][C]
    float inv0 = 1.f / l0, inv1 = 1.f / l1;
    size_t row = (size_t)(b * NV + qt * 64 + wid * 16 + qrow);
#pragma unroll
    for (int nt = 0; nt < 8; nt++) {
        int col = h * DV + nt * 8 + 2 * qc;
        *(float2*)&O[row * CV + col]       = make_float2(o[nt][0] * inv0, o[nt][1] * inv0);
        *(float2*)&O[(row + 8) * CV + col] = make_float2(o[nt][2] * inv1, o[nt][3] * inv1);
    }
}

// ---------------------------------------------------------------------------
extern "C" void kernel_launch(void* const* d_in, const int* in_sizes, int n_in,
                              void* d_out, int out_size)
{
    const float* x_t    = (const float*)d_in[0];
    const float* x_s    = (const float*)d_in[1];
    const float* W_q    = (const float*)d_in[2];
    const float* W_kv   = (const float*)d_in[3];
    const float* W_fuse = (const float*)d_in[4];
    const float* b_fuse = (const float*)d_in[5];
    float* out = (float*)d_out;

    float *Qp, *KVp, *Ap, *WqT, *WkvT, *WfT;
    cudaGetSymbolAddress((void**)&Qp,   g_Q);
    cudaGetSymbolAddress((void**)&KVp,  g_KV);
    cudaGetSymbolAddress((void**)&Ap,   g_A);
    cudaGetSymbolAddress((void**)&WqT,  g_WqT);
    cudaGetSymbolAddress((void**)&WkvT, g_WkvT);
    cudaGetSymbolAddress((void**)&WfT,  g_WfT);

    static bool attr_set = false;
    if (!attr_set) {
        cudaFuncSetAttribute(tcgemm, cudaFuncAttributeMaxDynamicSharedMemorySize,
                             GEMM_SMEM);
        attr_set = true;
    }

    const int M = BV * NV;  // 4096

    transp<<<dim3(CV / 32, CV / 32), dim3(32, 8)>>>(W_q, WqT, CV, CV);
    transp<<<dim3(2 * CV / 32, CV / 32), dim3(32, 8)>>>(W_kv, WkvT, CV, 2 * CV);
    transp<<<dim3(CV / 32, CV / 32), dim3(32, 8)>>>(W_fuse, WfT, CV, CV);

    tcgemm<<<dim3(CV / 128, M / 128), 256, GEMM_SMEM>>>(x_t, WqT, nullptr, Qp, M, CV, CV);
    tcgemm<<<dim3(2 * CV / 128, M / 128), 256, GEMM_SMEM>>>(x_s, WkvT, nullptr, KVp, M, 2 * CV, CV);
    tcattn<<<dim3(NV / 64, BV * HV), 128>>>(Qp, KVp, Ap);
    tcgemm<<<dim3(CV / 128, M / 128), 256, GEMM_SMEM>>>(Ap, WfT, b_fuse, out, M, CV, CV);
}

// round 5
// speedup vs baseline: 3.1736x; 1.0823x over previous
#include <cuda_runtime.h>
#include <math_constants.h>
#include <cstdint>

// Problem shape (fixed): B=2, N=2048, C=1024, H=16, D=64
#define BV 2
#define NV 2048
#define CV 1024
#define HV 16
#define DV 64
#define ATTN_SCALE 0.125f

// Scratch (__device__ globals; allocation-free rule)
__device__ float g_Q [BV * NV * CV];
__device__ float g_KV[BV * NV * 2 * CV];
__device__ float g_A [BV * NV * CV];

// ---------------------------------------------------------------------------
// helpers
// ---------------------------------------------------------------------------
__device__ __forceinline__ uint32_t f2tf(float x) {  // fp32 -> tf32 (RNA)
    uint32_t r;
    asm("cvt.rna.tf32.f32 %0, %1;" : "=r"(r) : "f"(x));
    return r;
}
__device__ __forceinline__ uint32_t f2tfb(uint32_t bits) {
    return f2tf(__uint_as_float(bits));
}
__device__ __forceinline__ void mma_tf32(float* d, const uint32_t* a,
                                         const uint32_t* b) {
    asm volatile(
        "mma.sync.aligned.m16n8k8.row.col.f32.tf32.tf32.f32 "
        "{%0,%1,%2,%3}, {%4,%5,%6,%7}, {%8,%9}, {%0,%1,%2,%3};"
        : "+f"(d[0]), "+f"(d[1]), "+f"(d[2]), "+f"(d[3])
        : "r"(a[0]), "r"(a[1]), "r"(a[2]), "r"(a[3]), "r"(b[0]), "r"(b[1]));
}
__device__ __forceinline__ uint32_t smem_u32(const void* p) {
    uint32_t a;
    asm("{ .reg .u64 t; cvta.to.shared.u64 t, %1; cvt.u32.u64 %0, t; }"
        : "=r"(a) : "l"(p));
    return a;
}
__device__ __forceinline__ void cpa16(uint32_t saddr, const void* gaddr) {
    asm volatile("cp.async.cg.shared.global [%0], [%1], 16;"
                 :: "r"(saddr), "l"(gaddr) : "memory");
}
__device__ __forceinline__ void cpa_commit() {
    asm volatile("cp.async.commit_group;" ::: "memory");
}
template <int N>
__device__ __forceinline__ void cpa_wait() {
    asm volatile("cp.async.wait_group %0;" :: "n"(N) : "memory");
}

// ---------------------------------------------------------------------------
// Tensor-core tf32 GEMM: C[M,N] = A[M,K] @ B[K,N] (+bias). No transpose needed.
// 128x128 tile, 256 threads / 8 warps, warp tile 64x32, K chunk 32.
// 3-stage cp.async pipeline; raw fp32 in smem, cvt->tf32 after fragment LDS.
// A smem: [128][32] pad 36 words (bank = (4r+c)%32, conflict-free).
// B smem: [32][128] pad 136 words (bank = (8k+n)%32 pattern, conflict-free).
// ---------------------------------------------------------------------------
#define GA_ST 4608            // A stage words (128*36)
#define GB_ST 4352            // B stage words (32*136)
#define GB_BASE (3 * GA_ST)   // 13824
#define GEMM_SMEM ((GB_BASE + 3 * GB_ST) * 4)   // 107520 B

__global__ __launch_bounds__(256, 1)
void tcgemm(const float* __restrict__ A, const float* __restrict__ B,
            const float* __restrict__ bias, float* __restrict__ C,
            int M, int N, int K)
{
    extern __shared__ __align__(16) uint32_t sm[];
    const uint32_t sb = smem_u32(sm);

    const int tid = threadIdx.x;
    const int wid = tid >> 5, lid = tid & 31;
    const int bm = blockIdx.y * 128, bn = blockIdx.x * 128;
    const int wm = (wid & 1) * 64;
    const int wn = (wid >> 1) * 32;
    const int qrow = lid >> 2, qc = lid & 3;

    const int NC = K >> 5;

    // per-thread load coordinates
    const int ar = tid >> 3, ac4 = (tid & 7) << 2;          // +32 rows per it
    const int br = tid >> 5, bn4 = (tid & 31) << 2;         // +8 rows per it

    auto issue = [&](int c, int st) {
        const int kc = c << 5;
        const uint32_t aB = sb + st * (GA_ST * 4);
        const uint32_t bB = sb + (GB_BASE + st * GB_ST) * 4;
#pragma unroll
        for (int it = 0; it < 4; it++) {
            int r = ar + it * 32;
            cpa16(aB + r * 144 + (ac4 << 2),
                  &A[(size_t)(bm + r) * K + kc + ac4]);
        }
#pragma unroll
        for (int it = 0; it < 4; it++) {
            int r = br + it * 8;
            cpa16(bB + r * 544 + (bn4 << 2),
                  &B[(size_t)(kc + r) * N + bn + bn4]);
        }
    };

    float acc[4][4][4];
#pragma unroll
    for (int mt = 0; mt < 4; mt++)
#pragma unroll
        for (int nt = 0; nt < 4; nt++)
#pragma unroll
            for (int r = 0; r < 4; r++) acc[mt][nt][r] = 0.f;

    // prologue: stages 0..2
    issue(0, 0); cpa_commit();
    issue(1, 1); cpa_commit();
    issue(2, 2); cpa_commit();

    int st = 0;
    for (int c = 0; c < NC; c++) {
        cpa_wait<2>();
        __syncthreads();

        const uint32_t* Ab = sm + st * GA_ST;
        const uint32_t* Bb = sm + GB_BASE + st * GB_ST;
#pragma unroll
        for (int ks = 0; ks < 4; ks++) {
            const int c0 = ks * 8 + qc;
            uint32_t af[4][4], bf[4][2];
#pragma unroll
            for (int mt = 0; mt < 4; mt++) {
                const uint32_t* base = Ab + (wm + qrow + mt * 16) * 36;
                af[mt][0] = f2tfb(base[c0]);
                af[mt][1] = f2tfb(base[8 * 36 + c0]);
                af[mt][2] = f2tfb(base[c0 + 4]);
                af[mt][3] = f2tfb(base[8 * 36 + c0 + 4]);
            }
#pragma unroll
            for (int nt = 0; nt < 4; nt++) {
                const int n = wn + nt * 8 + qrow;
                bf[nt][0] = f2tfb(Bb[c0 * 136 + n]);
                bf[nt][1] = f2tfb(Bb[(c0 + 4) * 136 + n]);
            }
#pragma unroll
            for (int mt = 0; mt < 4; mt++)
#pragma unroll
                for (int nt = 0; nt < 4; nt++)
                    mma_tf32(acc[mt][nt], af[mt], bf[nt]);
        }
        __syncthreads();
        if (c + 3 < NC) issue(c + 3, st);
        cpa_commit();   // always: keeps group accounting uniform
        st = (st + 1 == 3) ? 0 : st + 1;
    }

    // epilogue
#pragma unroll
    for (int mt = 0; mt < 4; mt++) {
        int row = bm + wm + mt * 16 + qrow;
#pragma unroll
        for (int nt = 0; nt < 4; nt++) {
            int col = bn + wn + nt * 8 + 2 * qc;
            float b0 = bias ? bias[col] : 0.f;
            float b1 = bias ? bias[col + 1] : 0.f;
            *(float2*)&C[(size_t)row * N + col] =
                make_float2(acc[mt][nt][0] + b0, acc[mt][nt][1] + b1);
            *(float2*)&C[(size_t)(row + 8) * N + col] =
                make_float2(acc[mt][nt][2] + b0, acc[mt][nt][3] + b1);
        }
    }
}

// ---------------------------------------------------------------------------
// Tensor-core flash attention, double-buffered cp.async K/V.
// Block = 128 threads / 4 warps; 64 q-rows of one (b,h); 32-key chunks.
// smem (dynamic, bytes): Qs[64][68] tf32 @0; K0@17408; K1@26112; V0@34816;
// V1@43520 (each [32][68] raw fp32); Ps[64][36] tf32 @52224. Total 61440.
// ---------------------------------------------------------------------------
#define ATT_SMEM 61440
#define KOFF (17408 / 4)
#define VOFF (34816 / 4)
#define POFF (52224 / 4)

__global__ __launch_bounds__(128)
void tcattn(const float* __restrict__ Q, const float* __restrict__ KV,
            float* __restrict__ O)
{
    extern __shared__ __align__(16) uint32_t sa[];
    const uint32_t sb = smem_u32(sa);

    const int tid  = threadIdx.x;
    const int wid  = tid >> 5, lid = tid & 31;
    const int qt   = blockIdx.x;
    const int b    = blockIdx.y >> 4;
    const int h    = blockIdx.y & 15;
    const int qrow = lid >> 2, qc = lid & 3;

    const float* qbase = Q  + ((size_t)(b * NV + qt * 64)) * CV + h * DV;
    const float* kbase = KV + (size_t)b * NV * 2 * CV + h * DV;
    const float* vbase = kbase + CV;

    // load Q tile (scaled, tf32) into Qs
#pragma unroll
    for (int it = 0; it < 8; it++) {
        int s = tid + it * 128;
        int r = s >> 4, c4 = (s & 15) << 2;
        float4 v = *(const float4*)&qbase[(size_t)r * CV + c4];
        *(uint4*)&sa[r * 68 + c4] =
            make_uint4(f2tf(v.x * ATTN_SCALE), f2tf(v.y * ATTN_SCALE),
                       f2tf(v.z * ATTN_SCALE), f2tf(v.w * ATTN_SCALE));
    }

    const int lr = tid >> 4, lc4 = (tid & 15) << 2;   // K/V load coords (+8 rows/it)
    auto issueKV = [&](int c0k, int buf) {
        const uint32_t kB = sb + (KOFF + buf * 2176) * 4;
        const uint32_t vB = sb + (VOFF + buf * 2176) * 4;
#pragma unroll
        for (int it = 0; it < 4; it++) {
            int r = lr + it * 8;
            cpa16(kB + r * 272 + (lc4 << 2), &kbase[(size_t)(c0k + r) * (2 * CV) + lc4]);
            cpa16(vB + r * 272 + (lc4 << 2), &vbase[(size_t)(c0k + r) * (2 * CV) + lc4]);
        }
    };

    float o[8][4];
#pragma unroll
    for (int nt = 0; nt < 8; nt++)
#pragma unroll
        for (int r = 0; r < 4; r++) o[nt][r] = 0.f;
    float m0 = -CUDART_INF_F, m1 = -CUDART_INF_F, l0 = 0.f, l1 = 0.f;

    issueKV(0, 0); cpa_commit();

    const int NCH = NV / 32;
    for (int c = 0; c < NCH; c++) {
        __syncthreads();   // all warps done with buffer being overwritten (and Qs on c=0)
        if (c + 1 < NCH) issueKV((c + 1) * 32, (c + 1) & 1);
        cpa_commit();
        cpa_wait<1>();     // chunk c landed
        __syncthreads();

        const uint32_t* Kb = sa + KOFF + (c & 1) * 2176;
        const uint32_t* Vb = sa + VOFF + (c & 1) * 2176;

        // ---- S = Q @ K^T : warp tile 16x32
        float s[4][4];
#pragma unroll
        for (int nt = 0; nt < 4; nt++)
#pragma unroll
            for (int r = 0; r < 4; r++) s[nt][r] = 0.f;
#pragma unroll
        for (int ks = 0; ks < 8; ks++) {
            const int cc = ks * 8 + qc;
            uint32_t af[4], bf[4][2];
            const uint32_t* qb = sa + (wid * 16 + qrow) * 68;
            af[0] = qb[cc];
            af[1] = qb[8 * 68 + cc];
            af[2] = qb[cc + 4];
            af[3] = qb[8 * 68 + cc + 4];
#pragma unroll
            for (int nt = 0; nt < 4; nt++) {
                const uint32_t* kb = Kb + (nt * 8 + qrow) * 68;
                bf[nt][0] = f2tfb(kb[cc]);
                bf[nt][1] = f2tfb(kb[cc + 4]);
            }
#pragma unroll
            for (int nt = 0; nt < 4; nt++)
                mma_tf32(s[nt], af, bf[nt]);
        }

        // ---- online softmax on fragments
        float mx0 = -CUDART_INF_F, mx1 = -CUDART_INF_F;
#pragma unroll
        for (int nt = 0; nt < 4; nt++) {
            mx0 = fmaxf(mx0, fmaxf(s[nt][0], s[nt][1]));
            mx1 = fmaxf(mx1, fmaxf(s[nt][2], s[nt][3]));
        }
        mx0 = fmaxf(mx0, __shfl_xor_sync(0xffffffffu, mx0, 1));
        mx0 = fmaxf(mx0, __shfl_xor_sync(0xffffffffu, mx0, 2));
        mx1 = fmaxf(mx1, __shfl_xor_sync(0xffffffffu, mx1, 1));
        mx1 = fmaxf(mx1, __shfl_xor_sync(0xffffffffu, mx1, 2));
        float mn0 = fmaxf(m0, mx0), mn1 = fmaxf(m1, mx1);
        float f0 = __expf(m0 - mn0), f1 = __expf(m1 - mn1);

        float rs0 = 0.f, rs1 = 0.f;
        uint32_t* Prow = sa + POFF + (wid * 16 + qrow) * 36;
#pragma unroll
        for (int nt = 0; nt < 4; nt++) {
            float p0 = __expf(s[nt][0] - mn0);
            float p1 = __expf(s[nt][1] - mn0);
            float p2 = __expf(s[nt][2] - mn1);
            float p3 = __expf(s[nt][3] - mn1);
            rs0 += p0 + p1;
            rs1 += p2 + p3;
            int pc = nt * 8 + 2 * qc;
            *(uint2*)&Prow[pc]          = make_uint2(f2tf(p0), f2tf(p1));
            *(uint2*)&Prow[8 * 36 + pc] = make_uint2(f2tf(p2), f2tf(p3));
        }
        rs0 += __shfl_xor_sync(0xffffffffu, rs0, 1);
        rs0 += __shfl_xor_sync(0xffffffffu, rs0, 2);
        rs1 += __shfl_xor_sync(0xffffffffu, rs1, 1);
        rs1 += __shfl_xor_sync(0xffffffffu, rs1, 2);
        l0 = l0 * f0 + rs0;  m0 = mn0;
        l1 = l1 * f1 + rs1;  m1 = mn1;
#pragma unroll
        for (int nt = 0; nt < 8; nt++) {
            o[nt][0] *= f0; o[nt][1] *= f0;
            o[nt][2] *= f1; o[nt][3] *= f1;
        }
        __syncwarp();

        // ---- O += P @ V
#pragma unroll
        for (int ks = 0; ks < 4; ks++) {
            const int kk = ks * 8 + qc;
            uint32_t af[4];
            const uint32_t* pb = sa + POFF + (wid * 16 + qrow) * 36;
            af[0] = pb[kk];
            af[1] = pb[8 * 36 + kk];
            af[2] = pb[kk + 4];
            af[3] = pb[8 * 36 + kk + 4];
#pragma unroll
            for (int nt = 0; nt < 8; nt++) {
                uint32_t bf[2];
                bf[0] = f2tfb(Vb[(ks * 8 + qc) * 68 + nt * 8 + qrow]);
                bf[1] = f2tfb(Vb[(ks * 8 + qc + 4) * 68 + nt * 8 + qrow]);
                mma_tf32(o[nt], af, bf);
            }
        }
        __syncwarp();   // Ps reused next iteration
    }

    // ---- write O (normalized)
    float inv0 = 1.f / l0, inv1 = 1.f / l1;
    size_t row = (size_t)(b * NV + qt * 64 + wid * 16 + qrow);
#pragma unroll
    for (int nt = 0; nt < 8; nt++) {
        int col = h * DV + nt * 8 + 2 * qc;
        *(float2*)&O[row * CV + col]       = make_float2(o[nt][0] * inv0, o[nt][1] * inv0);
        *(float2*)&O[(row + 8) * CV + col] = make_float2(o[nt][2] * inv1, o[nt][3] * inv1);
    }
}

// ---------------------------------------------------------------------------
extern "C" void kernel_launch(void* const* d_in, const int* in_sizes, int n_in,
                              void* d_out, int out_size)
{
    const float* x_t    = (const float*)d_in[0];
    const float* x_s    = (const float*)d_in[1];
    const float* W_q    = (const float*)d_in[2];
    const float* W_kv   = (const float*)d_in[3];
    const float* W_fuse = (const float*)d_in[4];
    const float* b_fuse = (const float*)d_in[5];
    float* out = (float*)d_out;

    float *Qp, *KVp, *Ap;
    cudaGetSymbolAddress((void**)&Qp,  g_Q);
    cudaGetSymbolAddress((void**)&KVp, g_KV);
    cudaGetSymbolAddress((void**)&Ap,  g_A);

    static bool attr_set = false;
    if (!attr_set) {
        cudaFuncSetAttribute(tcgemm, cudaFuncAttributeMaxDynamicSharedMemorySize,
                             GEMM_SMEM);
        cudaFuncSetAttribute(tcattn, cudaFuncAttributeMaxDynamicSharedMemorySize,
                             ATT_SMEM);
        attr_set = true;
    }

    const int M = BV * NV;  // 4096

    tcgemm<<<dim3(CV / 128, M / 128), 256, GEMM_SMEM>>>(x_t, W_q, nullptr, Qp, M, CV, CV);
    tcgemm<<<dim3(2 * CV / 128, M / 128), 256, GEMM_SMEM>>>(x_s, W_kv, nullptr, KVp, M, 2 * CV, CV);
    tcattn<<<dim3(NV / 64, BV * HV), 128, ATT_SMEM>>>(Qp, KVp, Ap);
    tcgemm<<<dim3(CV / 128, M / 128), 256, GEMM_SMEM>>>(Ap, W_fuse, b_fuse, out, M, CV, CV);
}

// round 6
// speedup vs baseline: 7.2964x; 2.2991x over previous
#include <cuda_runtime.h>
#include <cuda_fp16.h>
#include <math_constants.h>
#include <cstdint>

// Problem shape (fixed): B=2, N=2048, C=1024, H=16, D=64
#define BV 2
#define NV 2048
#define CV 1024
#define HV 16
#define DV 64
#define ATTN_SCALE 0.125f

// fp16 scratch (__device__ globals; allocation-free rule)
__device__ __half g_xth [BV * NV * CV];
__device__ __half g_xsh [BV * NV * CV];
__device__ __half g_Wqh [CV * CV];
__device__ __half g_Wkvh[CV * 2 * CV];
__device__ __half g_Wfh [CV * CV];
__device__ __half g_Qh  [BV * NV * CV];        // ATTN_SCALE folded in
__device__ __half g_KVh [BV * NV * 2 * CV];
__device__ __half g_Ah  [BV * NV * CV];

// ---------------------------------------------------------------------------
// helpers
// ---------------------------------------------------------------------------
__device__ __forceinline__ uint32_t smem_u32(const void* p) {
    uint32_t a;
    asm("{ .reg .u64 t; cvta.to.shared.u64 t, %1; cvt.u32.u64 %0, t; }"
        : "=r"(a) : "l"(p));
    return a;
}
__device__ __forceinline__ void cpa16(uint32_t saddr, const void* gaddr) {
    asm volatile("cp.async.cg.shared.global [%0], [%1], 16;"
                 :: "r"(saddr), "l"(gaddr) : "memory");
}
__device__ __forceinline__ void cpa_commit() {
    asm volatile("cp.async.commit_group;" ::: "memory");
}
template <int N>
__device__ __forceinline__ void cpa_wait() {
    asm volatile("cp.async.wait_group %0;" :: "n"(N) : "memory");
}
__device__ __forceinline__ void ldsm4(uint32_t* r, uint32_t addr) {
    asm volatile("ldmatrix.sync.aligned.m8n8.x4.shared.b16 {%0,%1,%2,%3}, [%4];"
                 : "=r"(r[0]), "=r"(r[1]), "=r"(r[2]), "=r"(r[3]) : "r"(addr));
}
__device__ __forceinline__ void ldsm4t(uint32_t* r, uint32_t addr) {
    asm volatile("ldmatrix.sync.aligned.m8n8.x4.trans.shared.b16 {%0,%1,%2,%3}, [%4];"
                 : "=r"(r[0]), "=r"(r[1]), "=r"(r[2]), "=r"(r[3]) : "r"(addr));
}
__device__ __forceinline__ void mma16(float* d, const uint32_t* a, const uint32_t* b) {
    asm volatile(
        "mma.sync.aligned.m16n8k16.row.col.f32.f16.f16.f32 "
        "{%0,%1,%2,%3}, {%4,%5,%6,%7}, {%8,%9}, {%0,%1,%2,%3};"
        : "+f"(d[0]), "+f"(d[1]), "+f"(d[2]), "+f"(d[3])
        : "r"(a[0]), "r"(a[1]), "r"(a[2]), "r"(a[3]), "r"(b[0]), "r"(b[1]));
}
__device__ __forceinline__ uint32_t packh2(float x, float y) {
    __half2 h = __floats2half2_rn(x, y);
    return *(uint32_t*)&h;
}

// ---------------------------------------------------------------------------
// fp32 -> fp16 bulk convert (8 elems/thread)
// ---------------------------------------------------------------------------
__global__ void f2h(const float4* __restrict__ in, uint4* __restrict__ outp, int n8)
{
    int i = blockIdx.x * 256 + threadIdx.x;
    if (i >= n8) return;
    float4 a = in[2 * i], b = in[2 * i + 1];
    uint4 o;
    o.x = packh2(a.x, a.y); o.y = packh2(a.z, a.w);
    o.z = packh2(b.x, b.y); o.w = packh2(b.z, b.w);
    outp[i] = o;
}

// ---------------------------------------------------------------------------
// fp16 tensor-core GEMM: C[M,N] = A[M,K] @ B[K,N].
// Output: fp16 (Ch, scaled) or fp32 (Cf, +bias).
// 128x128 tile, 256 thr / 8 warps, warp tile 64x32, K chunk 32, 3-stage
// cp.async. A smem [128][40] halves, B smem [32][136] halves (16B row pad
// -> every ldmatrix phase conflict-free).
// ---------------------------------------------------------------------------
#define HA_ST (128 * 40)        // halves per A stage
#define HB_ST (32 * 136)        // halves per B stage
#define HB_BASE (3 * HA_ST)
#define HGEMM_SMEM ((HB_BASE + 3 * HB_ST) * 2)   // 56832 B

__global__ __launch_bounds__(256, 2)
void hgemm(const __half* __restrict__ A, const __half* __restrict__ B,
           const float* __restrict__ bias, float* __restrict__ Cf,
           __half* __restrict__ Ch, float scale, int M, int N, int K)
{
    extern __shared__ __align__(16) __half hsm[];
    const uint32_t sb = smem_u32(hsm);

    const int tid = threadIdx.x;
    const int wid = tid >> 5, lid = tid & 31;
    const int bm = blockIdx.y * 128, bn = blockIdx.x * 128;
    const int wm = (wid & 1) * 64, wn = (wid >> 1) * 32;
    const int qrow = lid >> 2, qc = lid & 3;
    const int l15 = lid & 15, l16 = (lid >> 4) * 8;

    const int NC = K >> 5;

    auto issue = [&](int c, int st) {
        const int kc = c << 5;
        const uint32_t aB = sb + st * HA_ST * 2;
        const uint32_t bB = sb + (HB_BASE + st * HB_ST) * 2;
#pragma unroll
        for (int it = 0; it < 2; it++) {
            int idx = tid + it * 256;
            int r = idx >> 2, ch = idx & 3;            // A: 128 rows x 4 chunks
            cpa16(aB + (r * 40 + ch * 8) * 2,
                  &A[(size_t)(bm + r) * K + kc + ch * 8]);
        }
#pragma unroll
        for (int it = 0; it < 2; it++) {
            int idx = tid + it * 256;
            int r = idx >> 4, ch = idx & 15;           // B: 32 rows x 16 chunks
            cpa16(bB + (r * 136 + ch * 8) * 2,
                  &B[(size_t)(kc + r) * N + bn + ch * 8]);
        }
    };

    float acc[4][4][4];
#pragma unroll
    for (int mt = 0; mt < 4; mt++)
#pragma unroll
        for (int nt = 0; nt < 4; nt++)
#pragma unroll
            for (int r = 0; r < 4; r++) acc[mt][nt][r] = 0.f;

    issue(0, 0); cpa_commit();
    issue(1, 1); cpa_commit();
    issue(2, 2); cpa_commit();

    int st = 0;
    for (int c = 0; c < NC; c++) {
        cpa_wait<2>();
        __syncthreads();
        const uint32_t Ab = sb + st * HA_ST * 2;
        const uint32_t Bb = sb + (HB_BASE + st * HB_ST) * 2;
#pragma unroll
        for (int ks = 0; ks < 2; ks++) {
            uint32_t af[4][4], bf[4][2];
#pragma unroll
            for (int mt = 0; mt < 4; mt++)
                ldsm4(af[mt], Ab + ((wm + mt * 16 + l15) * 40 + ks * 16 + l16) * 2);
#pragma unroll
            for (int np = 0; np < 2; np++) {
                uint32_t t[4];
                ldsm4t(t, Bb + ((ks * 16 + l15) * 136 + wn + np * 16 + l16) * 2);
                bf[np * 2][0] = t[0]; bf[np * 2][1] = t[1];
                bf[np * 2 + 1][0] = t[2]; bf[np * 2 + 1][1] = t[3];
            }
#pragma unroll
            for (int mt = 0; mt < 4; mt++)
#pragma unroll
                for (int nt = 0; nt < 4; nt++)
                    mma16(acc[mt][nt], af[mt], bf[nt]);
        }
        __syncthreads();
        if (c + 3 < NC) issue(c + 3, st);
        cpa_commit();
        st = (st + 1 == 3) ? 0 : st + 1;
    }

    // epilogue
#pragma unroll
    for (int mt = 0; mt < 4; mt++) {
        int row = bm + wm + mt * 16 + qrow;
#pragma unroll
        for (int nt = 0; nt < 4; nt++) {
            int col = bn + wn + nt * 8 + 2 * qc;
            if (Ch) {
                *(uint32_t*)&Ch[(size_t)row * N + col] =
                    packh2(acc[mt][nt][0] * scale, acc[mt][nt][1] * scale);
                *(uint32_t*)&Ch[(size_t)(row + 8) * N + col] =
                    packh2(acc[mt][nt][2] * scale, acc[mt][nt][3] * scale);
            } else {
                float b0 = bias ? bias[col] : 0.f;
                float b1 = bias ? bias[col + 1] : 0.f;
                *(float2*)&Cf[(size_t)row * N + col] =
                    make_float2(acc[mt][nt][0] + b0, acc[mt][nt][1] + b1);
                *(float2*)&Cf[(size_t)(row + 8) * N + col] =
                    make_float2(acc[mt][nt][2] + b0, acc[mt][nt][3] + b1);
            }
        }
    }
}

// ---------------------------------------------------------------------------
// fp16 tensor-core flash attention. 128 thr / 4 warps; 64 q-rows per block;
// 64-key chunks, double-buffered cp.async K/V. Q pre-scaled fp16 in g_Qh.
// smem (halves): Qs[64][72]@0, K0/K1@4608, V0/V1@13824, Ps[64][72]@23040.
// ---------------------------------------------------------------------------
#define AQ_OFF 0
#define AK_OFF 4608
#define AV_OFF 13824
#define AP_OFF 23040
#define HATT_SMEM ((23040 + 4608) * 2)   // 55296 B

__global__ __launch_bounds__(128)
void hattn(const __half* __restrict__ Q, const __half* __restrict__ KV,
           __half* __restrict__ O)
{
    extern __shared__ __align__(16) __half sa[];
    const uint32_t sb = smem_u32(sa);

    const int tid  = threadIdx.x;
    const int wid  = tid >> 5, lid = tid & 31;
    const int qt   = blockIdx.x;
    const int b    = blockIdx.y >> 4;
    const int h    = blockIdx.y & 15;
    const int qrow = lid >> 2, qc = lid & 3;
    const int l15 = lid & 15, l16 = (lid >> 4) * 8;
    const int l7 = lid & 7, l8h = ((lid >> 3) & 1) * 8;

    const __half* qbase = Q  + ((size_t)(b * NV + qt * 64)) * CV + h * DV;
    const __half* kbase = KV + (size_t)b * NV * 2 * CV + h * DV;
    const __half* vbase = kbase + CV;

    // Q tile -> smem (cp.async, group 0)
#pragma unroll
    for (int it = 0; it < 4; it++) {
        int idx = tid + it * 128;
        int r = idx >> 3, ch = idx & 7;
        cpa16(sb + (r * 72 + ch * 8) * 2, &qbase[(size_t)r * CV + ch * 8]);
    }
    cpa_commit();

    auto issueKV = [&](int key0, int buf) {
        const uint32_t kB = sb + (AK_OFF + buf * 4608) * 2;
        const uint32_t vB = sb + (AV_OFF + buf * 4608) * 2;
#pragma unroll
        for (int it = 0; it < 4; it++) {
            int idx = tid + it * 128;
            int r = idx >> 3, ch = idx & 7;
            cpa16(kB + (r * 72 + ch * 8) * 2,
                  &kbase[(size_t)(key0 + r) * (2 * CV) + ch * 8]);
            cpa16(vB + (r * 72 + ch * 8) * 2,
                  &vbase[(size_t)(key0 + r) * (2 * CV) + ch * 8]);
        }
    };
    issueKV(0, 0); cpa_commit();

    float o[8][4];
#pragma unroll
    for (int nt = 0; nt < 8; nt++)
#pragma unroll
        for (int r = 0; r < 4; r++) o[nt][r] = 0.f;
    float m0 = -CUDART_INF_F, m1 = -CUDART_INF_F, l0 = 0.f, l1 = 0.f;
    uint32_t qf[4][4];

    const int NCH = NV / 64;
    for (int c = 0; c < NCH; c++) {
        __syncthreads();   // all warps done with buffer being overwritten
        if (c + 1 < NCH) issueKV((c + 1) * 64, (c + 1) & 1);
        cpa_commit();
        cpa_wait<1>();     // Q (c==0) and KV chunk c landed
        __syncthreads();

        if (c == 0) {      // Q fragments once (persist in regs)
#pragma unroll
            for (int ks = 0; ks < 4; ks++)
                ldsm4(qf[ks], sb + ((wid * 16 + l15) * 72 + ks * 16 + l16) * 2);
        }

        const uint32_t Kb = sb + (AK_OFF + (c & 1) * 4608) * 2;
        const uint32_t Vb = sb + (AV_OFF + (c & 1) * 4608) * 2;

        // ---- S = Q @ K^T (16 q x 64 keys per warp)
        float s[8][4];
#pragma unroll
        for (int nt = 0; nt < 8; nt++)
#pragma unroll
            for (int r = 0; r < 4; r++) s[nt][r] = 0.f;
#pragma unroll
        for (int np = 0; np < 4; np++) {
#pragma unroll
            for (int ks = 0; ks < 4; ks++) {
                uint32_t t[4];
                ldsm4(t, Kb + ((np * 16 + l16 + l7) * 72 + ks * 16 + l8h) * 2);
                mma16(s[np * 2],     qf[ks], t);
                mma16(s[np * 2 + 1], qf[ks], t + 2);
            }
        }

        // ---- online softmax on fragments
        float mx0 = -CUDART_INF_F, mx1 = -CUDART_INF_F;
#pragma unroll
        for (int nt = 0; nt < 8; nt++) {
            mx0 = fmaxf(mx0, fmaxf(s[nt][0], s[nt][1]));
            mx1 = fmaxf(mx1, fmaxf(s[nt][2], s[nt][3]));
        }
        mx0 = fmaxf(mx0, __shfl_xor_sync(0xffffffffu, mx0, 1));
        mx0 = fmaxf(mx0, __shfl_xor_sync(0xffffffffu, mx0, 2));
        mx1 = fmaxf(mx1, __shfl_xor_sync(0xffffffffu, mx1, 1));
        mx1 = fmaxf(mx1, __shfl_xor_sync(0xffffffffu, mx1, 2));
        float mn0 = fmaxf(m0, mx0), mn1 = fmaxf(m1, mx1);
        float f0 = __expf(m0 - mn0), f1 = __expf(m1 - mn1);

        float rs0 = 0.f, rs1 = 0.f;
        __half* Prow = sa + AP_OFF + (wid * 16 + qrow) * 72;
#pragma unroll
        for (int nt = 0; nt < 8; nt++) {
            float p0 = __expf(s[nt][0] - mn0);
            float p1 = __expf(s[nt][1] - mn0);
            float p2 = __expf(s[nt][2] - mn1);
            float p3 = __expf(s[nt][3] - mn1);
            rs0 += p0 + p1;  rs1 += p2 + p3;
            *(uint32_t*)&Prow[nt * 8 + 2 * qc]          = packh2(p0, p1);
            *(uint32_t*)&Prow[8 * 72 + nt * 8 + 2 * qc] = packh2(p2, p3);
        }
        rs0 += __shfl_xor_sync(0xffffffffu, rs0, 1);
        rs0 += __shfl_xor_sync(0xffffffffu, rs0, 2);
        rs1 += __shfl_xor_sync(0xffffffffu, rs1, 1);
        rs1 += __shfl_xor_sync(0xffffffffu, rs1, 2);
        l0 = l0 * f0 + rs0;  m0 = mn0;
        l1 = l1 * f1 + rs1;  m1 = mn1;
#pragma unroll
        for (int nt = 0; nt < 8; nt++) {
            o[nt][0] *= f0; o[nt][1] *= f0;
            o[nt][2] *= f1; o[nt][3] *= f1;
        }
        __syncwarp();   // P visible to whole warp

        // ---- O += P @ V
        const uint32_t Pb = sb + (AP_OFF + wid * 16 * 72) * 2;
#pragma unroll
        for (int ks = 0; ks < 4; ks++) {
            uint32_t pf[4];
            ldsm4(pf, Pb + (l15 * 72 + ks * 16 + l16) * 2);
#pragma unroll
            for (int dp = 0; dp < 4; dp++) {
                uint32_t t[4];
                ldsm4t(t, Vb + ((ks * 16 + l15) * 72 + dp * 16 + l16) * 2);
                mma16(o[dp * 2],     pf, t);
                mma16(o[dp * 2 + 1], pf, t + 2);
            }
        }
        __syncwarp();   // P reused next chunk
    }

    // ---- write O (normalized) as fp16
    float inv0 = 1.f / l0, inv1 = 1.f / l1;
    size_t row = (size_t)(b * NV + qt * 64 + wid * 16 + qrow);
#pragma unroll
    for (int nt = 0; nt < 8; nt++) {
        int col = h * DV + nt * 8 + 2 * qc;
        *(uint32_t*)&O[row * CV + col]       = packh2(o[nt][0] * inv0, o[nt][1] * inv0);
        *(uint32_t*)&O[(row + 8) * CV + col] = packh2(o[nt][2] * inv1, o[nt][3] * inv1);
    }
}

// ---------------------------------------------------------------------------
extern "C" void kernel_launch(void* const* d_in, const int* in_sizes, int n_in,
                              void* d_out, int out_size)
{
    const float* x_t    = (const float*)d_in[0];
    const float* x_s    = (const float*)d_in[1];
    const float* W_q    = (const float*)d_in[2];
    const float* W_kv   = (const float*)d_in[3];
    const float* W_fuse = (const float*)d_in[4];
    const float* b_fuse = (const float*)d_in[5];
    float* out = (float*)d_out;

    __half *xth, *xsh, *Wqh, *Wkvh, *Wfh, *Qh, *KVh, *Ah;
    cudaGetSymbolAddress((void**)&xth,  g_xth);
    cudaGetSymbolAddress((void**)&xsh,  g_xsh);
    cudaGetSymbolAddress((void**)&Wqh,  g_Wqh);
    cudaGetSymbolAddress((void**)&Wkvh, g_Wkvh);
    cudaGetSymbolAddress((void**)&Wfh,  g_Wfh);
    cudaGetSymbolAddress((void**)&Qh,   g_Qh);
    cudaGetSymbolAddress((void**)&KVh,  g_KVh);
    cudaGetSymbolAddress((void**)&Ah,   g_Ah);

    static bool attr_set = false;
    if (!attr_set) {
        cudaFuncSetAttribute(hgemm, cudaFuncAttributeMaxDynamicSharedMemorySize,
                             HGEMM_SMEM);
        cudaFuncSetAttribute(hattn, cudaFuncAttributeMaxDynamicSharedMemorySize,
                             HATT_SMEM);
        attr_set = true;
    }

    const int M = BV * NV;  // 4096

    // fp32 -> fp16 conversions
    f2h<<<(BV * NV * CV / 8) / 256, 256>>>((const float4*)x_t, (uint4*)xth, BV * NV * CV / 8);
    f2h<<<(BV * NV * CV / 8) / 256, 256>>>((const float4*)x_s, (uint4*)xsh, BV * NV * CV / 8);
    f2h<<<(CV * CV / 8) / 256, 256>>>((const float4*)W_q, (uint4*)Wqh, CV * CV / 8);
    f2h<<<(CV * 2 * CV / 8) / 256, 256>>>((const float4*)W_kv, (uint4*)Wkvh, CV * 2 * CV / 8);
    f2h<<<(CV * CV / 8) / 256, 256>>>((const float4*)W_fuse, (uint4*)Wfh, CV * CV / 8);

    // Q = (x_t @ W_q) * ATTN_SCALE   (fp16 out)
    hgemm<<<dim3(CV / 128, M / 128), 256, HGEMM_SMEM>>>(
        xth, Wqh, nullptr, nullptr, Qh, ATTN_SCALE, M, CV, CV);
    // KV = x_s @ W_kv                (fp16 out)
    hgemm<<<dim3(2 * CV / 128, M / 128), 256, HGEMM_SMEM>>>(
        xsh, Wkvh, nullptr, nullptr, KVh, 1.f, M, 2 * CV, CV);
    // A = softmax(Q K^T) V           (fp16 out)
    hattn<<<dim3(NV / 64, BV * HV), 128, HATT_SMEM>>>(Qh, KVh, Ah);
    // out = A @ W_fuse + b_fuse      (fp32 out)
    hgemm<<<dim3(CV / 128, M / 128), 256, HGEMM_SMEM>>>(
        Ah, Wfh, b_fuse, out, nullptr, 1.f, M, CV, CV);
}